// round 7
// baseline (speedup 1.0000x reference)
#include <cuda_runtime.h>
#include <cuda_fp16.h>
#include <cstdint>

// B=4, N=4096, D=256
// scores = (V V^T)/16 ; edges = softsign(scores)
// dstate = edges @ state ; dval = edges @ val
// Phase A: hh in fp16 HMMA + cross terms (hl, lh) in e4m3 QMMA k32 (residuals
// scaled x2048). Phase B: 1-term fp16 (E * V_hi). cp.async double-buffered.

#define BATCH 4
#define NN 4096
#define DD 256
#define BM 128
#define BJH 32
#define NHALF (NN / BJH)
#define THREADS 256
#define ROWB 528     // fp16 row pitch (132 words, bank-step 4: conflict-free ldsm)
#define ROW8 272     // fp8 row pitch  (68 words,  bank-step 4: conflict-free ldsm)

// smem layout (bytes)
static constexpr uint32_t S_VIH  = 0;                        // Vi fp16 hi 128x528 = 67584
static constexpr uint32_t S_VI8H = 67584;                    // Vi fp8 hi 128x272 = 34816
static constexpr uint32_t S_VI8L = 102400;                   // Vi fp8 lo(x2048)
static constexpr uint32_t S_VJ0  = 137216;                   // buffer0
static constexpr uint32_t VJ8H   = 16896;                    // fp8 hi offset within buffer
static constexpr uint32_t VJ8L   = 25600;                    // fp8 lo offset
static constexpr uint32_t VJBUF  = 34304;                    // buffer size
static constexpr uint32_t S_VJ1  = S_VJ0 + VJBUF;            // 171520
static constexpr uint32_t S_ST0  = S_VJ1 + VJBUF;            // 205824
static constexpr uint32_t S_ST1  = S_ST0 + 128;
static constexpr uint32_t SMEM_BYTES = S_ST1 + 128;          // 206080

__device__ __half  g_vhi[(size_t)BATCH * NN * DD];
__device__ uint8_t g_v8h[(size_t)BATCH * NN * DD];
__device__ uint8_t g_v8l[(size_t)BATCH * NN * DD];

__device__ __forceinline__ uint32_t smem_u32(const void* p) {
    uint32_t a;
    asm("{ .reg .u64 t; cvta.to.shared.u64 t, %1; cvt.u32.u64 %0, t; }" : "=r"(a) : "l"(p));
    return a;
}
__device__ __forceinline__ void cpa16(uint32_t dst, const void* src) {
    asm volatile("cp.async.cg.shared.global [%0], [%1], 16;" :: "r"(dst), "l"(src) : "memory");
}
#define CP_COMMIT() asm volatile("cp.async.commit_group;" ::: "memory")
#define CP_WAIT1()  asm volatile("cp.async.wait_group 1;" ::: "memory")

__device__ __forceinline__ void ldm_x4(uint32_t* r, uint32_t addr) {
    asm volatile("ldmatrix.sync.aligned.m8n8.x4.shared.b16 {%0,%1,%2,%3}, [%4];"
        : "=r"(r[0]), "=r"(r[1]), "=r"(r[2]), "=r"(r[3]) : "r"(addr));
}
__device__ __forceinline__ void ldm_x4_t(uint32_t* r, uint32_t addr) {
    asm volatile("ldmatrix.sync.aligned.m8n8.x4.trans.shared.b16 {%0,%1,%2,%3}, [%4];"
        : "=r"(r[0]), "=r"(r[1]), "=r"(r[2]), "=r"(r[3]) : "r"(addr));
}
__device__ __forceinline__ void mma16816(float* c, const uint32_t* a, const uint32_t* b) {
    asm volatile("mma.sync.aligned.m16n8k16.row.col.f32.f16.f16.f32 "
        "{%0,%1,%2,%3}, {%4,%5,%6,%7}, {%8,%9}, {%0,%1,%2,%3};"
        : "+f"(c[0]), "+f"(c[1]), "+f"(c[2]), "+f"(c[3])
        : "r"(a[0]), "r"(a[1]), "r"(a[2]), "r"(a[3]), "r"(b[0]), "r"(b[1]));
}
__device__ __forceinline__ void mmafp8(float* c, const uint32_t* a, const uint32_t* b) {
    asm volatile("mma.sync.aligned.m16n8k32.row.col.f32.e4m3.e4m3.f32 "
        "{%0,%1,%2,%3}, {%4,%5,%6,%7}, {%8,%9}, {%0,%1,%2,%3};"
        : "+f"(c[0]), "+f"(c[1]), "+f"(c[2]), "+f"(c[3])
        : "r"(a[0]), "r"(a[1]), "r"(a[2]), "r"(a[3]), "r"(b[0]), "r"(b[1]));
}
__device__ __forceinline__ uint32_t h2pk(float x, float y) {
    __half2 t = __floats2half2_rn(x, y);
    return *reinterpret_cast<uint32_t*>(&t);
}
// pack 4 floats -> 4 e4m3 bytes (byte i = x_i), satfinite
__device__ __forceinline__ uint32_t e4m3x4(float x0, float x1, float x2, float x3) {
    uint16_t lo, hi;
    asm("cvt.rn.satfinite.e4m3x2.f32 %0, %1, %2;" : "=h"(lo) : "f"(x1), "f"(x0));
    asm("cvt.rn.satfinite.e4m3x2.f32 %0, %1, %2;" : "=h"(hi) : "f"(x3), "f"(x2));
    return (uint32_t)lo | ((uint32_t)hi << 16);
}

// ---------------- pre-kernel: fp32 -> fp16 hi, e4m3 hi, e4m3 scaled residual ----------------
__global__ __launch_bounds__(256) void split_kernel(const float* __restrict__ val) {
    const int b = blockIdx.y, n0 = blockIdx.x * 64;
    const size_t base = ((size_t)b * NN + n0) * DD;
    #pragma unroll
    for (int k = 0; k < 8; k++) {
        size_t u = (size_t)(threadIdx.x + 256 * k) * 8;
        const float* p = val + base + u;
        float v[8];
        *(float4*)(v)     = *(const float4*)(p);
        *(float4*)(v + 4) = *(const float4*)(p + 4);
        float r[8];
        #pragma unroll
        for (int j = 0; j < 8; j++)
            r[j] = (v[j] - __half2float(__float2half_rn(v[j]))) * 2048.0f;
        uint4 h;
        h.x = h2pk(v[0], v[1]); h.y = h2pk(v[2], v[3]);
        h.z = h2pk(v[4], v[5]); h.w = h2pk(v[6], v[7]);
        *(uint4*)(g_vhi + base + u) = h;
        *(uint2*)(g_v8h + base + u) =
            make_uint2(e4m3x4(v[0], v[1], v[2], v[3]), e4m3x4(v[4], v[5], v[6], v[7]));
        *(uint2*)(g_v8l + base + u) =
            make_uint2(e4m3x4(r[0], r[1], r[2], r[3]), e4m3x4(r[4], r[5], r[6], r[7]));
    }
}

// ---------------- main kernel ----------------
__global__ __launch_bounds__(THREADS, 1)
void prop_hmma(const float* __restrict__ state,
               float* __restrict__ dstate, float* __restrict__ dval)
{
    extern __shared__ char smem[];
    const uint32_t sb = smem_u32(smem);
    const int tid = threadIdx.x, l = tid & 31, wid = tid >> 5;
    const int b = blockIdx.y, i0 = blockIdx.x * BM;
    const int mrow = wid * 16;
    const size_t vbase = (size_t)b * NN * DD;

    // ---- prologue fill: Vi (fp16 hi + fp8 hi/lo) + j-half 0 ----
    {
        #pragma unroll
        for (int k = 0; k < 16; k++) {            // Vi fp16 hi: 4096 chunks
            int u = tid + 256 * k;
            int row = u >> 5, ch = u & 31;
            cpa16(sb + S_VIH + (uint32_t)(row * ROWB + ch * 16),
                  g_vhi + vbase + (size_t)(i0 + row) * DD + ch * 8);
        }
        #pragma unroll
        for (int k = 0; k < 16; k++) {            // Vi fp8 hi+lo: 4096 chunks
            int u = tid + 256 * k;
            int t8 = u >> 11, rem = u & 2047;     // 0=hi,1=lo
            int row = rem >> 4, ch = rem & 15;
            cpa16(sb + (t8 ? S_VI8L : S_VI8H) + (uint32_t)(row * ROW8 + ch * 16),
                  (t8 ? g_v8l : g_v8h) + vbase + (size_t)(i0 + row) * DD + ch * 16);
        }
        #pragma unroll
        for (int k = 0; k < 8; k++) {             // Vj half 0
            int u = tid + 256 * k;
            if (u < 1024) {                        // fp16 hi: 32 rows x 32 ch
                int row = u >> 5, ch = u & 31;
                cpa16(sb + S_VJ0 + (uint32_t)(row * ROWB + ch * 16),
                      g_vhi + vbase + (size_t)row * DD + ch * 8);
            } else {                               // fp8 hi+lo: 1024 chunks
                int u2 = u - 1024;
                int t8 = u2 >> 9, rem = u2 & 511;
                int row = rem >> 4, ch = rem & 15;
                cpa16(sb + S_VJ0 + (t8 ? VJ8L : VJ8H) + (uint32_t)(row * ROW8 + ch * 16),
                      (t8 ? g_v8l : g_v8h) + vbase + (size_t)row * DD + ch * 16);
            }
        }
        if (tid < 8) cpa16(sb + S_ST0 + tid * 16, state + (size_t)b * NN + tid * 4);
        CP_COMMIT();
    }

    const uint32_t offA  = (uint32_t)((l & 15) * ROWB + (l >> 4) * 16);
    const uint32_t offA8 = (uint32_t)((l & 15) * ROW8 + (l >> 4) * 16);
    const uint32_t offBn = (uint32_t)(((l & 7) + ((l & 16) ? 8 : 0)) * ROWB + ((l >> 3) & 1) * 16);
    const uint32_t offB8 = (uint32_t)(((l & 7) + ((l & 16) ? 8 : 0)) * ROW8 + ((l >> 3) & 1) * 16);
    const uint32_t viH  = sb + S_VIH  + mrow * ROWB + offA;
    const uint32_t vi8H = sb + S_VI8H + mrow * ROW8 + offA8;
    const uint32_t vi8L = sb + S_VI8L + mrow * ROW8 + offA8;

    float dacc[32][4];
    #pragma unroll
    for (int t = 0; t < 32; t++) { dacc[t][0] = dacc[t][1] = dacc[t][2] = dacc[t][3] = 0.f; }
    float ds0 = 0.f, ds1 = 0.f;
    const float scale = 0.0625f;
    const int c0 = 2 * (l & 3);

    for (int h = 0; h < NHALF; h++) {
        // ---- issue fill(h+1) ----
        {
            int hn = h + 1;
            if (hn < NHALF) {
                const int j0 = hn * BJH;
                uint32_t bufb = sb + ((hn & 1) ? S_VJ1 : S_VJ0);
                #pragma unroll
                for (int k = 0; k < 8; k++) {
                    int u = tid + 256 * k;
                    if (u < 1024) {
                        int row = u >> 5, ch = u & 31;
                        cpa16(bufb + (uint32_t)(row * ROWB + ch * 16),
                              g_vhi + vbase + (size_t)(j0 + row) * DD + ch * 8);
                    } else {
                        int u2 = u - 1024;
                        int t8 = u2 >> 9, rem = u2 & 511;
                        int row = rem >> 4, ch = rem & 15;
                        cpa16(bufb + (t8 ? VJ8L : VJ8H) + (uint32_t)(row * ROW8 + ch * 16),
                              (t8 ? g_v8l : g_v8h) + vbase + (size_t)(j0 + row) * DD + ch * 16);
                    }
                }
                if (tid < 8)
                    cpa16(sb + ((hn & 1) ? S_ST1 : S_ST0) + tid * 16,
                          state + (size_t)b * NN + j0 + tid * 4);
            }
            CP_COMMIT();
        }
        CP_WAIT1();
        __syncthreads();

        const uint32_t bufb = sb + ((h & 1) ? S_VJ1 : S_VJ0);
        const uint32_t vjB  = bufb + offBn;             // fp16 hi, phase A B
        const uint32_t vjT  = bufb + offA;              // fp16 hi, phase B B (trans)
        const uint32_t vj8H = bufb + VJ8H + offB8;
        const uint32_t vj8L = bufb + VJ8L + offB8;
        const float* stp = (const float*)(smem + ((h & 1) ? S_ST1 : S_ST0));

        float sacc[4][4], s8acc[4][4];
        #pragma unroll
        for (int t = 0; t < 4; t++) {
            sacc[t][0] = sacc[t][1] = sacc[t][2] = sacc[t][3] = 0.f;
            s8acc[t][0] = s8acc[t][1] = s8acc[t][2] = s8acc[t][3] = 0.f;
        }

        // ---- Phase A1: hh fp16, 16 k16-steps ----
        #pragma unroll
        for (int s = 0; s < 16; s++) {
            uint32_t ah[4], bh0[4], bh1[4];
            ldm_x4(ah, viH + s * 32);
            ldm_x4(bh0, vjB + s * 32);
            ldm_x4(bh1, vjB + 16 * ROWB + s * 32);
            mma16816(sacc[0], ah, bh0 + 0);
            mma16816(sacc[1], ah, bh0 + 2);
            mma16816(sacc[2], ah, bh1 + 0);
            mma16816(sacc[3], ah, bh1 + 2);
        }

        // ---- Phase A2: cross terms fp8, 8 k32-steps ----
        #pragma unroll
        for (int s = 0; s < 8; s++) {
            uint32_t a8h[4], a8l[4], b8h0[4], b8h1[4], b8l0[4], b8l1[4];
            ldm_x4(a8h, vi8H + s * 32);
            ldm_x4(a8l, vi8L + s * 32);
            ldm_x4(b8h0, vj8H + s * 32);
            ldm_x4(b8h1, vj8H + 16 * ROW8 + s * 32);
            ldm_x4(b8l0, vj8L + s * 32);
            ldm_x4(b8l1, vj8L + 16 * ROW8 + s * 32);
            // hl: a_hi(fp8) x b_lo(scaled fp8)
            mmafp8(s8acc[0], a8h, b8l0 + 0);
            mmafp8(s8acc[1], a8h, b8l0 + 2);
            mmafp8(s8acc[2], a8h, b8l1 + 0);
            mmafp8(s8acc[3], a8h, b8l1 + 2);
            // lh: a_lo(scaled fp8) x b_hi(fp8)
            mmafp8(s8acc[0], a8l, b8h0 + 0);
            mmafp8(s8acc[1], a8l, b8h0 + 2);
            mmafp8(s8acc[2], a8l, b8h1 + 0);
            mmafp8(s8acc[3], a8l, b8h1 + 2);
        }

        // ---- epilogue: combine, softsign, dstate partial, E fp16 a-frags ----
        uint32_t eh[2][4];
        const float inv2048 = 1.0f / 2048.0f;
        #pragma unroll
        for (int t = 0; t < 4; t++) {
            float f0 = (sacc[t][0] + s8acc[t][0] * inv2048) * scale;
            float f1 = (sacc[t][1] + s8acc[t][1] * inv2048) * scale;
            float f2 = (sacc[t][2] + s8acc[t][2] * inv2048) * scale;
            float f3 = (sacc[t][3] + s8acc[t][3] * inv2048) * scale;
            float e0 = __fdividef(f0, 1.0f + fabsf(f0));
            float e1 = __fdividef(f1, 1.0f + fabsf(f1));
            float e2 = __fdividef(f2, 1.0f + fabsf(f2));
            float e3 = __fdividef(f3, 1.0f + fabsf(f3));
            float sA = stp[8 * t + c0], sB = stp[8 * t + c0 + 1];
            ds0 += e0 * sA + e1 * sB;
            ds1 += e2 * sA + e3 * sB;
            int kt = t >> 1, hh = (t & 1) * 2;
            eh[kt][hh]     = h2pk(e0, e1);
            eh[kt][hh + 1] = h2pk(e2, e3);
        }

        // ---- Phase B: 1-term (E fp16 x V_hi), blocks of 4, distance 8 ----
        #pragma unroll
        for (int kt = 0; kt < 2; kt++) {
            uint32_t tb = vjT + kt * (16 * ROWB);
            #pragma unroll
            for (int blk = 0; blk < 4; blk++) {
                uint32_t bh[4][4];
                #pragma unroll
                for (int j = 0; j < 4; j++)
                    ldm_x4_t(bh[j], tb + (blk * 4 + j) * 32);
                #pragma unroll
                for (int j = 0; j < 4; j++) {
                    int nt2 = blk * 4 + j;
                    mma16816(dacc[2 * nt2],     eh[kt], bh[j] + 0);
                    mma16816(dacc[2 * nt2 + 1], eh[kt], bh[j] + 2);
                }
            }
        }
        __syncthreads();
    }

    // ---- write dval ----
    {
        const int row = i0 + mrow + (l >> 2);
        float* d0 = dval + (size_t)b * NN * DD + (size_t)row * DD;
        float* d1 = d0 + 8 * DD;
        #pragma unroll
        for (int nt = 0; nt < 32; nt++) {
            int c = 8 * nt + c0;
            *(float2*)(d0 + c) = make_float2(dacc[nt][0], dacc[nt][1]);
            *(float2*)(d1 + c) = make_float2(dacc[nt][2], dacc[nt][3]);
        }
    }
    // ---- dstate ----
    ds0 += __shfl_xor_sync(0xFFFFFFFFu, ds0, 1);
    ds0 += __shfl_xor_sync(0xFFFFFFFFu, ds0, 2);
    ds1 += __shfl_xor_sync(0xFFFFFFFFu, ds1, 1);
    ds1 += __shfl_xor_sync(0xFFFFFFFFu, ds1, 2);
    if ((l & 3) == 0) {
        int r = i0 + mrow + (l >> 2);
        dstate[(size_t)b * NN + r]     = ds0;
        dstate[(size_t)b * NN + r + 8] = ds1;
    }
}

extern "C" void kernel_launch(void* const* d_in, const int* in_sizes, int n_in,
                              void* d_out, int out_size)
{
    const float* val   = (const float*)d_in[0];   // [B, N, D]
    const float* state = (const float*)d_in[1];   // [B, N]
    float* dstate = (float*)d_out;                // [B, N]
    float* dval   = dstate + (size_t)BATCH * NN;  // [B, N, D]
    (void)in_sizes; (void)n_in; (void)out_size;

    dim3 gs(NN / 64, BATCH);
    split_kernel<<<gs, 256>>>(val);

    cudaFuncSetAttribute(prop_hmma,
                         cudaFuncAttributeMaxDynamicSharedMemorySize, (int)SMEM_BYTES);
    dim3 grid(NN / BM, BATCH);
    prop_hmma<<<grid, THREADS, SMEM_BYTES>>>(state, dstate, dval);
}